// round 11
// baseline (speedup 1.0000x reference)
#include <cuda_runtime.h>
#include <cuda_bf16.h>
#include <math.h>

// Problem constants
#define B 2
#define N 1024
#define G0 40            // coarse grid per axis
#define DHW 128          // fine grid per axis
#define INV_ALPHA 200.0f // 1/0.005
#define BETA 0.01f
#define T2 1e-10f        // weight cutoff: E2*max(E1) <= T2 -> term dropped

// ---------------- scratch (device globals; no allocations allowed) ----------
__device__ float  g_E0[B * N * G0];       // [b][n][i]  exp(-(a_i-c0)^2/alpha)
__device__ float  g_E1[B * G0 * N];       // [b][j][n]
__device__ float  g_E2[B * G0 * N];       // [b][k][n]
__device__ float  g_vals[B * 3 * N];      // [b][c][n]  = -offsets
__device__ float4 g_F[B * G0 * G0 * G0];  // [b][k][j][i] -> {f0,f1,f2,pad}

// ---------------- Kernel 0: per-axis exp tables ------------------------------
// Thread map: n fastest (t = idx & 2047), i = idx >> 11  -> coalesced input
// loads and coalesced E1/E2 stores; only E0's store is strided (1 of 3).
__global__ __launch_bounds__(256) void table_kernel(const float* __restrict__ cpc,
                                                    const float* __restrict__ cpo) {
    int idx = blockIdx.x * 256 + threadIdx.x;   // 0 .. B*N*G0-1 = 81919
    if (idx >= B * N * G0) return;
    int t = idx & (B * N - 1);   // b*N + n   (B*N = 2048, power of 2)
    int i = idx >> 11;           // 0..39
    int b = t >> 10;
    int n = t & (N - 1);

    float o0 = cpo[t * 3 + 0], o1 = cpo[t * 3 + 1], o2 = cpo[t * 3 + 2];
    float c0 = cpc[t * 3 + 0] + o0;
    float c1 = cpc[t * 3 + 1] + o1;
    float c2 = cpc[t * 3 + 2] + o2;

    if (i == 0) {
        g_vals[(b * 3 + 0) * N + n] = -o0;
        g_vals[(b * 3 + 1) * N + n] = -o1;
        g_vals[(b * 3 + 2) * N + n] = -o2;
    }

    const float step = 2.0f / (float)(G0 - 1);
    float a = fmaf((float)i, step, -1.0f);
    float d0 = a - c0, d1 = a - c1, d2 = a - c2;
    g_E0[(size_t)t * G0 + i]   = __expf(-d0 * d0 * INV_ALPHA);
    g_E1[(b * G0 + i) * N + n] = __expf(-d1 * d1 * INV_ALPHA);
    g_E2[(b * G0 + i) * N + n] = __expf(-d2 * d2 * INV_ALPHA);
}

// ---------------- Kernel A: sparse coarse displacement field -----------------
__global__ __launch_bounds__(256) void coarse_kernel() {
    __shared__ float4 sPack[N];       // {n_as_float, v0, v1, v2}
    __shared__ float  sW[4 * N];      // [jl][slot] = E1[j][n]*E2[k][n]
    __shared__ int    sCnt[8];
    __shared__ int    sBase[9];

    int jt = blockIdx.x;   // 0..9
    int k  = blockIdx.y;   // 0..39
    int b  = blockIdx.z;   // 0..1
    int tid  = threadIdx.x;
    int wid  = tid >> 5, lane = tid & 31;

    const float* E2k = &g_E2[(b * G0 + k) * N];
    const float* E1b = &g_E1[(b * G0 + jt * 4) * N];
    const float* Vb  = &g_vals[b * 3 * N];

    // ---- phase A: survivor ballots (order-preserving) ----
    unsigned bal[4];
    int cnt = 0;
#pragma unroll
    for (int it = 0; it < 4; it++) {
        int n = wid * 128 + it * 32 + lane;
        float e2 = E2k[n];
        bool p = false;
        if (e2 > T2) {
            float m = fmaxf(fmaxf(E1b[n], E1b[N + n]),
                            fmaxf(E1b[2 * N + n], E1b[3 * N + n]));
            p = (e2 * m > T2);
        }
        bal[it] = __ballot_sync(0xffffffffu, p);
        cnt += __popc(bal[it]);
    }
    if (lane == 0) sCnt[wid] = cnt;
    __syncthreads();
    if (tid == 0) {
        int acc = 0;
        for (int w = 0; w < 8; w++) { sBase[w] = acc; acc += sCnt[w]; }
        sBase[8] = acc;
    }
    __syncthreads();

    // ---- phase B: ordered compaction ----
    int off = sBase[wid];
#pragma unroll
    for (int it = 0; it < 4; it++) {
        unsigned bl = bal[it];
        if (bl & (1u << lane)) {
            int n = wid * 128 + it * 32 + lane;
            float e2 = E2k[n];
            int slot = off + __popc(bl & ((1u << lane) - 1u));
            float4 pv;
            pv.x = __int_as_float(n);
            pv.y = Vb[n];
            pv.z = Vb[N + n];
            pv.w = Vb[2 * N + n];
            sPack[slot] = pv;
            sW[0 * N + slot] = e2 * E1b[n];
            sW[1 * N + slot] = e2 * E1b[N + n];
            sW[2 * N + slot] = e2 * E1b[2 * N + n];
            sW[3 * N + slot] = e2 * E1b[3 * N + n];
        }
        off += __popc(bl);
    }
    __syncthreads();
    int total = sBase[8];

    // ---- phase C: dense accumulation over survivors ----
    if (tid < 160) {
        int i  = tid % 40;
        int jl = tid / 40;
        const float* E0b  = &g_E0[(size_t)(b * N) * G0 + i];
        const float* wrow = &sW[jl * N];

        float s = 0.f, a0 = 0.f, a1 = 0.f, a2 = 0.f;
#pragma unroll 4
        for (int t = 0; t < total; t++) {
            float4 pv = sPack[t];
            float  w  = wrow[t] * E0b[__float_as_int(pv.x) * G0];
            s  += w;
            a0 = fmaf(w, pv.y, a0);
            a1 = fmaf(w, pv.z, a1);
            a2 = fmaf(w, pv.w, a2);
        }
        float inv = (BETA + 1.0f) / (s + BETA);
        float4 r;
        r.x = a0 * inv; r.y = a1 * inv; r.z = a2 * inv; r.w = 0.f;
        int j = jt * 4 + jl;
        g_F[((b * G0 + k) * G0 + j) * G0 + i] = r;
    }
}

// ---------------- Kernel B: upsample flow + grid_sample (4 voxels/thread) ----
__global__ __launch_bounds__(256) void warp_kernel(const float* __restrict__ mask,
                                                   float* __restrict__ out) {
    int q = blockIdx.x * blockDim.x + threadIdx.x;  // 0 .. 2*128*128*32-1
    int ew = (q & 31) << 2;       // first of 4 consecutive w indices
    int h  = (q >> 5) & 127;
    int d  = (q >> 12) & 127;
    int b  = q >> 19;

    // ---- coarse j/k coords (F.interpolate align_corners=False) ----
    const float scale = (float)G0 / (float)DHW;  // 0.3125
    float ck = fmaxf(((float)d + 0.5f) * scale - 0.5f, 0.0f);
    float cj = fmaxf(((float)h + 0.5f) * scale - 0.5f, 0.0f);

    int k0 = min((int)ck, G0 - 1); int k1 = min(k0 + 1, G0 - 1); float fk = ck - (float)k0;
    int j0 = min((int)cj, G0 - 1); int j1 = min(j0 + 1, G0 - 1); float fj = cj - (float)j0;

    float gj = 1.0f - fj, gk = 1.0f - fk;
    float w00 = gj * gk, w01 = gj * fk, w10 = fj * gk, w11 = fj * fk;

    // ---- i-slot window: the 4 voxels' coarse x spans <= 2 cells ----
    float ci0 = fmaxf(((float)ew + 0.5f) * scale - 0.5f, 0.0f);
    int i0min = min((int)ci0, G0 - 1);
    int m0 = i0min;
    int m1 = min(i0min + 1, G0 - 1);
    int m2 = min(i0min + 2, G0 - 1);

    const float4* Fb = &g_F[b * G0 * G0 * G0];
    int r00 = (k0 * G0 + j0) * G0;
    int r01 = (k0 * G0 + j1) * G0;
    int r10 = (k1 * G0 + j0) * G0;
    int r11 = (k1 * G0 + j1) * G0;

    // accumulate (j,k)-blended flow at the 3 i-slots
    float P0x = 0.f, P0y = 0.f, P0z = 0.f;
    float P1x = 0.f, P1y = 0.f, P1z = 0.f;
    float P2x = 0.f, P2y = 0.f, P2z = 0.f;
    {
        float4 a, c, e;
        a = Fb[r00 + m0]; c = Fb[r00 + m1]; e = Fb[r00 + m2];
        P0x = fmaf(w00, a.x, P0x); P0y = fmaf(w00, a.y, P0y); P0z = fmaf(w00, a.z, P0z);
        P1x = fmaf(w00, c.x, P1x); P1y = fmaf(w00, c.y, P1y); P1z = fmaf(w00, c.z, P1z);
        P2x = fmaf(w00, e.x, P2x); P2y = fmaf(w00, e.y, P2y); P2z = fmaf(w00, e.z, P2z);
        a = Fb[r01 + m0]; c = Fb[r01 + m1]; e = Fb[r01 + m2];
        P0x = fmaf(w10, a.x, P0x); P0y = fmaf(w10, a.y, P0y); P0z = fmaf(w10, a.z, P0z);
        P1x = fmaf(w10, c.x, P1x); P1y = fmaf(w10, c.y, P1y); P1z = fmaf(w10, c.z, P1z);
        P2x = fmaf(w10, e.x, P2x); P2y = fmaf(w10, e.y, P2y); P2z = fmaf(w10, e.z, P2z);
        a = Fb[r10 + m0]; c = Fb[r10 + m1]; e = Fb[r10 + m2];
        P0x = fmaf(w01, a.x, P0x); P0y = fmaf(w01, a.y, P0y); P0z = fmaf(w01, a.z, P0z);
        P1x = fmaf(w01, c.x, P1x); P1y = fmaf(w01, c.y, P1y); P1z = fmaf(w01, c.z, P1z);
        P2x = fmaf(w01, e.x, P2x); P2y = fmaf(w01, e.y, P2y); P2z = fmaf(w01, e.z, P2z);
        a = Fb[r11 + m0]; c = Fb[r11 + m1]; e = Fb[r11 + m2];
        P0x = fmaf(w11, a.x, P0x); P0y = fmaf(w11, a.y, P0y); P0z = fmaf(w11, a.z, P0z);
        P1x = fmaf(w11, c.x, P1x); P1y = fmaf(w11, c.y, P1y); P1z = fmaf(w11, c.z, P1z);
        P2x = fmaf(w11, e.x, P2x); P2y = fmaf(w11, e.y, P2y); P2z = fmaf(w11, e.z, P2z);
    }

    const float lstep = 2.0f / (float)(DHW - 1);
    const float* mb = mask + b * (DHW * DHW * DHW);
    float basey = fmaf((float)h, lstep, -1.0f);
    float basez = fmaf((float)d, lstep, -1.0f);

    float4 res;
    float* rp = &res.x;

#pragma unroll
    for (int el = 0; el < 4; el++) {
        int e = ew + el;
        float ci = fmaxf(((float)e + 0.5f) * scale - 0.5f, 0.0f);
        int i0 = min((int)ci, G0 - 1);
        float fi = ci - (float)i0;
        float gi = 1.0f - fi;
        int s = i0 - i0min;   // 0 or 1

        float Ax = s ? P1x : P0x, Ay = s ? P1y : P0y, Az = s ? P1z : P0z;
        float Bx = s ? P2x : P1x, By = s ? P2y : P1y, Bz = s ? P2z : P1z;

        float f0 = gi * Ax + fi * Bx;
        float f1 = gi * Ay + fi * By;
        float f2 = gi * Az + fi * Bz;

        float gx = fmaf((float)e, lstep, -1.0f) + f0;
        float gy = basey + f1;
        float gz = basez + f2;

        float x = fmaf(gx, 64.0f, 63.5f);
        float y = fmaf(gy, 64.0f, 63.5f);
        float z = fmaf(gz, 64.0f, 63.5f);

        int ix = (int)floorf(x); float fx = x - (float)ix;
        int iy = (int)floorf(y); float fy = y - (float)iy;
        int iz = (int)floorf(z); float fz = z - (float)iz;
        float qx = 1.0f - fx, qy = 1.0f - fy, qz = 1.0f - fz;

        float acc = 0.0f;
#pragma unroll
        for (int dz = 0; dz < 2; dz++) {
            int zi = iz + dz;
            if ((unsigned)zi >= (unsigned)DHW) continue;
            float wz = dz ? fz : qz;
            const float* mz = mb + (zi << 14);
#pragma unroll
            for (int dy = 0; dy < 2; dy++) {
                int yi = iy + dy;
                if ((unsigned)yi >= (unsigned)DHW) continue;
                float wzy = wz * (dy ? fy : qy);
                const float* mzy = mz + (yi << 7);
#pragma unroll
                for (int dx = 0; dx < 2; dx++) {
                    int xi = ix + dx;
                    if ((unsigned)xi >= (unsigned)DHW) continue;
                    acc = fmaf(wzy * (dx ? fx : qx), mzy[xi], acc);
                }
            }
        }
        rp[el] = acc;
    }

    int obase = (((b << 7) | d) << 14) | (h << 7) | ew;
    *reinterpret_cast<float4*>(out + obase) = res;
}

// ---------------- launch ------------------------------------------------------
extern "C" void kernel_launch(void* const* d_in, const int* in_sizes, int n_in,
                              void* d_out, int out_size) {
    const float* mask = (const float*)d_in[0];  // (2,1,128,128,128)
    const float* cpc  = (const float*)d_in[1];  // (2,1024,3)
    const float* cpo  = (const float*)d_in[2];  // (2,1024,3)
    float* out = (float*)d_out;                 // (2,1,128,128,128)

    table_kernel<<<(B * N * G0 + 255) / 256, 256>>>(cpc, cpo);
    coarse_kernel<<<dim3(G0 / 4, G0, B), 256>>>();
    int nthreads = B * DHW * DHW * (DHW / 4);   // 4 voxels per thread
    warp_kernel<<<nthreads / 256, 256>>>(mask, out);
}

// round 12
// speedup vs baseline: 1.1148x; 1.1148x over previous
#include <cuda_runtime.h>
#include <cuda_bf16.h>
#include <math.h>

// Problem constants
#define B 2
#define N 1024
#define G0 40            // coarse grid per axis
#define DHW 128          // fine grid per axis
#define INV_ALPHA 200.0f // 1/0.005
#define BETA 0.01f
#define T2 1e-10f        // weight cutoff: E2*max(E1) <= T2 -> term dropped

// ---------------- scratch (device globals; no allocations allowed) ----------
__device__ float  g_E0[B * N * G0];       // [b][n][i]  exp(-(a_i-c0)^2/alpha)
__device__ float  g_E1[B * G0 * N];       // [b][j][n]
__device__ float  g_E2[B * G0 * N];       // [b][k][n]
__device__ float  g_vals[B * 3 * N];      // [b][c][n]  = -offsets
__device__ float4 g_F[B * G0 * G0 * G0];  // [b][k][j][i] -> {f0,f1,f2,pad}

// ---------------- Kernel 0: per-axis exp tables ------------------------------
__global__ __launch_bounds__(256) void table_kernel(const float* __restrict__ cpc,
                                                    const float* __restrict__ cpo) {
    int idx = blockIdx.x * 256 + threadIdx.x;   // 0 .. B*N*G0-1 = 81919
    if (idx >= B * N * G0) return;
    int t = idx & (B * N - 1);   // b*N + n
    int i = idx >> 11;           // 0..39
    int b = t >> 10;
    int n = t & (N - 1);

    float o0 = cpo[t * 3 + 0], o1 = cpo[t * 3 + 1], o2 = cpo[t * 3 + 2];
    float c0 = cpc[t * 3 + 0] + o0;
    float c1 = cpc[t * 3 + 1] + o1;
    float c2 = cpc[t * 3 + 2] + o2;

    if (i == 0) {
        g_vals[(b * 3 + 0) * N + n] = -o0;
        g_vals[(b * 3 + 1) * N + n] = -o1;
        g_vals[(b * 3 + 2) * N + n] = -o2;
    }

    const float step = 2.0f / (float)(G0 - 1);
    float a = fmaf((float)i, step, -1.0f);
    float d0 = a - c0, d1 = a - c1, d2 = a - c2;
    g_E0[(size_t)t * G0 + i]   = __expf(-d0 * d0 * INV_ALPHA);
    g_E1[(b * G0 + i) * N + n] = __expf(-d1 * d1 * INV_ALPHA);
    g_E2[(b * G0 + i) * N + n] = __expf(-d2 * d2 * INV_ALPHA);
}

// ---------------- Kernel A: sparse coarse displacement field -----------------
__global__ __launch_bounds__(256) void coarse_kernel() {
    __shared__ float4 sPack[N];
    __shared__ float  sW[4 * N];
    __shared__ int    sCnt[8];
    __shared__ int    sBase[9];

    int jt = blockIdx.x;   // 0..9
    int k  = blockIdx.y;   // 0..39
    int b  = blockIdx.z;   // 0..1
    int tid  = threadIdx.x;
    int wid  = tid >> 5, lane = tid & 31;

    const float* E2k = &g_E2[(b * G0 + k) * N];
    const float* E1b = &g_E1[(b * G0 + jt * 4) * N];
    const float* Vb  = &g_vals[b * 3 * N];

    unsigned bal[4];
    int cnt = 0;
#pragma unroll
    for (int it = 0; it < 4; it++) {
        int n = wid * 128 + it * 32 + lane;
        float e2 = E2k[n];
        bool p = false;
        if (e2 > T2) {
            float m = fmaxf(fmaxf(E1b[n], E1b[N + n]),
                            fmaxf(E1b[2 * N + n], E1b[3 * N + n]));
            p = (e2 * m > T2);
        }
        bal[it] = __ballot_sync(0xffffffffu, p);
        cnt += __popc(bal[it]);
    }
    if (lane == 0) sCnt[wid] = cnt;
    __syncthreads();
    if (tid == 0) {
        int acc = 0;
        for (int w = 0; w < 8; w++) { sBase[w] = acc; acc += sCnt[w]; }
        sBase[8] = acc;
    }
    __syncthreads();

    int off = sBase[wid];
#pragma unroll
    for (int it = 0; it < 4; it++) {
        unsigned bl = bal[it];
        if (bl & (1u << lane)) {
            int n = wid * 128 + it * 32 + lane;
            float e2 = E2k[n];
            int slot = off + __popc(bl & ((1u << lane) - 1u));
            float4 pv;
            pv.x = __int_as_float(n);
            pv.y = Vb[n];
            pv.z = Vb[N + n];
            pv.w = Vb[2 * N + n];
            sPack[slot] = pv;
            sW[0 * N + slot] = e2 * E1b[n];
            sW[1 * N + slot] = e2 * E1b[N + n];
            sW[2 * N + slot] = e2 * E1b[2 * N + n];
            sW[3 * N + slot] = e2 * E1b[3 * N + n];
        }
        off += __popc(bl);
    }
    __syncthreads();
    int total = sBase[8];

    if (tid < 160) {
        int i  = tid % 40;
        int jl = tid / 40;
        const float* E0b  = &g_E0[(size_t)(b * N) * G0 + i];
        const float* wrow = &sW[jl * N];

        float s = 0.f, a0 = 0.f, a1 = 0.f, a2 = 0.f;
#pragma unroll 4
        for (int t = 0; t < total; t++) {
            float4 pv = sPack[t];
            float  w  = wrow[t] * E0b[__float_as_int(pv.x) * G0];
            s  += w;
            a0 = fmaf(w, pv.y, a0);
            a1 = fmaf(w, pv.z, a1);
            a2 = fmaf(w, pv.w, a2);
        }
        float inv = (BETA + 1.0f) / (s + BETA);
        float4 r;
        r.x = a0 * inv; r.y = a1 * inv; r.z = a2 * inv; r.w = 0.f;
        int j = jt * 4 + jl;
        g_F[((b * G0 + k) * G0 + j) * G0 + i] = r;
    }
}

// ---------------- Kernel B: smem-tiled flow + grid_sample --------------------
// Block = 256 threads covering a (32 x, 8 h) voxel tile at fixed (d, b).
// Coarse footprint = 12 i-slots x 4 j-slots x 2 k-slots = 96 float4 staged in smem.
__global__ __launch_bounds__(256) void warp_kernel(const float* __restrict__ mask,
                                                   float* __restrict__ out) {
    __shared__ float4 sF[2 * 4 * 12];   // [k][j][i]

    int tid = threadIdx.x;
    int tx  = tid & 31;         // x within tile
    int ty  = tid >> 5;         // h within tile
    int xt  = blockIdx.x & 3;   // 4 x-tiles
    int ht  = blockIdx.x >> 2;  // 16 h-tiles
    int d   = blockIdx.y;
    int b   = blockIdx.z;
    int x0  = xt << 5;
    int h0  = ht << 3;

    const float scale = (float)G0 / (float)DHW;  // 0.3125

    // block-uniform coarse window
    float ck = fmaxf(((float)d + 0.5f) * scale - 0.5f, 0.0f);
    int k0 = min((int)ck, G0 - 1); int k1 = min(k0 + 1, G0 - 1);
    float fk = ck - (float)k0;

    float cj0 = fmaxf(((float)h0 + 0.5f) * scale - 0.5f, 0.0f);
    int j_base = min((int)cj0, G0 - 1);
    float ci0 = fmaxf(((float)x0 + 0.5f) * scale - 0.5f, 0.0f);
    int i_base = min((int)ci0, G0 - 1);

    // cooperative tile load: 96 float4
    if (tid < 96) {
        int li = tid % 12;
        int lj = (tid / 12) & 3;
        int lk = tid / 48;
        int ri = min(i_base + li, G0 - 1);
        int rj = min(j_base + lj, G0 - 1);
        int rk = lk ? k1 : k0;
        sF[tid] = g_F[((b * G0 + rk) * G0 + rj) * G0 + ri];
    }
    __syncthreads();

    // per-voxel coarse coords
    int x = x0 + tx;
    int h = h0 + ty;
    float ci = fmaxf(((float)x + 0.5f) * scale - 0.5f, 0.0f);
    int i0 = min((int)ci, G0 - 1);
    float fi = ci - (float)i0;
    int s0 = i0 - i_base;
    int s1 = min(i0 + 1, G0 - 1) - i_base;

    float cj = fmaxf(((float)h + 0.5f) * scale - 0.5f, 0.0f);
    int j0 = min((int)cj, G0 - 1);
    float fj = cj - (float)j0;
    int t0 = j0 - j_base;
    int t1 = min(j0 + 1, G0 - 1) - j_base;

    float4 v000 = sF[(0 * 4 + t0) * 12 + s0];
    float4 v001 = sF[(0 * 4 + t0) * 12 + s1];
    float4 v010 = sF[(0 * 4 + t1) * 12 + s0];
    float4 v011 = sF[(0 * 4 + t1) * 12 + s1];
    float4 v100 = sF[(1 * 4 + t0) * 12 + s0];
    float4 v101 = sF[(1 * 4 + t0) * 12 + s1];
    float4 v110 = sF[(1 * 4 + t1) * 12 + s0];
    float4 v111 = sF[(1 * 4 + t1) * 12 + s1];

    float gi = 1.0f - fi, gj = 1.0f - fj, gk = 1.0f - fk;
    float w00 = gj * gk, w01 = gj * fk, w10 = fj * gk, w11 = fj * fk;

    float f0 = gi * (w00 * v000.x + w10 * v010.x + w01 * v100.x + w11 * v110.x)
             + fi * (w00 * v001.x + w10 * v011.x + w01 * v101.x + w11 * v111.x);
    float f1 = gi * (w00 * v000.y + w10 * v010.y + w01 * v100.y + w11 * v110.y)
             + fi * (w00 * v001.y + w10 * v011.y + w01 * v101.y + w11 * v111.y);
    float f2 = gi * (w00 * v000.z + w10 * v010.z + w01 * v100.z + w11 * v110.z)
             + fi * (w00 * v001.z + w10 * v011.z + w01 * v101.z + w11 * v111.z);

    // warped grid coords (base + flow), then to sample space
    const float lstep = 2.0f / (float)(DHW - 1);
    float gx = fmaf((float)x, lstep, -1.0f) + f0;
    float gy = fmaf((float)h, lstep, -1.0f) + f1;
    float gz = fmaf((float)d, lstep, -1.0f) + f2;

    float xs = fmaf(gx, 64.0f, 63.5f);
    float ys = fmaf(gy, 64.0f, 63.5f);
    float zs = fmaf(gz, 64.0f, 63.5f);

    int ix = (int)floorf(xs); float fx = xs - (float)ix;
    int iy = (int)floorf(ys); float fy = ys - (float)iy;
    int iz = (int)floorf(zs); float fz = zs - (float)iz;
    float qx = 1.0f - fx, qy = 1.0f - fy, qz = 1.0f - fz;

    const float* mb = mask + b * (DHW * DHW * DHW);

    float acc = 0.0f;
#pragma unroll
    for (int dz = 0; dz < 2; dz++) {
        int zi = iz + dz;
        if ((unsigned)zi >= (unsigned)DHW) continue;
        float wz = dz ? fz : qz;
        const float* mz = mb + (zi << 14);
#pragma unroll
        for (int dy = 0; dy < 2; dy++) {
            int yi = iy + dy;
            if ((unsigned)yi >= (unsigned)DHW) continue;
            float wzy = wz * (dy ? fy : qy);
            const float* mzy = mz + (yi << 7);
#pragma unroll
            for (int dx = 0; dx < 2; dx++) {
                int xi = ix + dx;
                if ((unsigned)xi >= (unsigned)DHW) continue;
                acc = fmaf(wzy * (dx ? fx : qx), mzy[xi], acc);
            }
        }
    }

    out[(((b << 7) | d) << 14) | (h << 7) | x] = acc;
}

// ---------------- launch ------------------------------------------------------
extern "C" void kernel_launch(void* const* d_in, const int* in_sizes, int n_in,
                              void* d_out, int out_size) {
    const float* mask = (const float*)d_in[0];  // (2,1,128,128,128)
    const float* cpc  = (const float*)d_in[1];  // (2,1024,3)
    const float* cpo  = (const float*)d_in[2];  // (2,1024,3)
    float* out = (float*)d_out;                 // (2,1,128,128,128)

    table_kernel<<<(B * N * G0 + 255) / 256, 256>>>(cpc, cpo);
    coarse_kernel<<<dim3(G0 / 4, G0, B), 256>>>();
    warp_kernel<<<dim3(64, DHW, B), 256>>>(mask, out);
}

// round 13
// speedup vs baseline: 1.2887x; 1.1559x over previous
#include <cuda_runtime.h>
#include <cuda_bf16.h>
#include <math.h>

// Problem constants
#define B 2
#define N 1024
#define G0 40            // coarse grid per axis
#define DHW 128          // fine grid per axis
#define INV_ALPHA 200.0f // 1/0.005
#define BETA 0.01f
#define T2 1e-10f        // weight cutoff: E2*max(E1) <= T2 -> term dropped

// ---------------- scratch (device globals; no allocations allowed) ----------
__device__ float  g_E0[B * N * G0];       // [b][n][i]
__device__ float  g_E1[B * G0 * N];       // [b][j][n]
__device__ float  g_E2[B * G0 * N];       // [b][k][n]
__device__ float  g_vals[B * 3 * N];      // [b][c][n]
__device__ float4 g_F[B * G0 * G0 * G0];  // [b][k][j][i]

// ---------------- Kernel 0: per-axis exp tables ------------------------------
__global__ __launch_bounds__(256) void table_kernel(const float* __restrict__ cpc,
                                                    const float* __restrict__ cpo) {
    int idx = blockIdx.x * 256 + threadIdx.x;
    if (idx >= B * N * G0) return;
    int t = idx & (B * N - 1);
    int i = idx >> 11;
    int b = t >> 10;
    int n = t & (N - 1);

    float o0 = cpo[t * 3 + 0], o1 = cpo[t * 3 + 1], o2 = cpo[t * 3 + 2];
    float c0 = cpc[t * 3 + 0] + o0;
    float c1 = cpc[t * 3 + 1] + o1;
    float c2 = cpc[t * 3 + 2] + o2;

    if (i == 0) {
        g_vals[(b * 3 + 0) * N + n] = -o0;
        g_vals[(b * 3 + 1) * N + n] = -o1;
        g_vals[(b * 3 + 2) * N + n] = -o2;
    }

    const float step = 2.0f / (float)(G0 - 1);
    float a = fmaf((float)i, step, -1.0f);
    float d0 = a - c0, d1 = a - c1, d2 = a - c2;
    g_E0[(size_t)t * G0 + i]   = __expf(-d0 * d0 * INV_ALPHA);
    g_E1[(b * G0 + i) * N + n] = __expf(-d1 * d1 * INV_ALPHA);
    g_E2[(b * G0 + i) * N + n] = __expf(-d2 * d2 * INV_ALPHA);
}

// ---------------- Kernel A: sparse coarse displacement field -----------------
__global__ __launch_bounds__(256) void coarse_kernel() {
    __shared__ float4 sPack[N];
    __shared__ float  sW[4 * N];
    __shared__ int    sCnt[8];
    __shared__ int    sBase[9];

    int jt = blockIdx.x;
    int k  = blockIdx.y;
    int b  = blockIdx.z;
    int tid  = threadIdx.x;
    int wid  = tid >> 5, lane = tid & 31;

    const float* E2k = &g_E2[(b * G0 + k) * N];
    const float* E1b = &g_E1[(b * G0 + jt * 4) * N];
    const float* Vb  = &g_vals[b * 3 * N];

    unsigned bal[4];
    int cnt = 0;
#pragma unroll
    for (int it = 0; it < 4; it++) {
        int n = wid * 128 + it * 32 + lane;
        float e2 = E2k[n];
        bool p = false;
        if (e2 > T2) {
            float m = fmaxf(fmaxf(E1b[n], E1b[N + n]),
                            fmaxf(E1b[2 * N + n], E1b[3 * N + n]));
            p = (e2 * m > T2);
        }
        bal[it] = __ballot_sync(0xffffffffu, p);
        cnt += __popc(bal[it]);
    }
    if (lane == 0) sCnt[wid] = cnt;
    __syncthreads();
    if (tid == 0) {
        int acc = 0;
        for (int w = 0; w < 8; w++) { sBase[w] = acc; acc += sCnt[w]; }
        sBase[8] = acc;
    }
    __syncthreads();

    int off = sBase[wid];
#pragma unroll
    for (int it = 0; it < 4; it++) {
        unsigned bl = bal[it];
        if (bl & (1u << lane)) {
            int n = wid * 128 + it * 32 + lane;
            float e2 = E2k[n];
            int slot = off + __popc(bl & ((1u << lane) - 1u));
            float4 pv;
            pv.x = __int_as_float(n);
            pv.y = Vb[n];
            pv.z = Vb[N + n];
            pv.w = Vb[2 * N + n];
            sPack[slot] = pv;
            sW[0 * N + slot] = e2 * E1b[n];
            sW[1 * N + slot] = e2 * E1b[N + n];
            sW[2 * N + slot] = e2 * E1b[2 * N + n];
            sW[3 * N + slot] = e2 * E1b[3 * N + n];
        }
        off += __popc(bl);
    }
    __syncthreads();
    int total = sBase[8];

    if (tid < 160) {
        int i  = tid % 40;
        int jl = tid / 40;
        const float* E0b  = &g_E0[(size_t)(b * N) * G0 + i];
        const float* wrow = &sW[jl * N];

        float s = 0.f, a0 = 0.f, a1 = 0.f, a2 = 0.f;
#pragma unroll 4
        for (int t = 0; t < total; t++) {
            float4 pv = sPack[t];
            float  w  = wrow[t] * E0b[__float_as_int(pv.x) * G0];
            s  += w;
            a0 = fmaf(w, pv.y, a0);
            a1 = fmaf(w, pv.z, a1);
            a2 = fmaf(w, pv.w, a2);
        }
        float inv = (BETA + 1.0f) / (s + BETA);
        float4 r;
        r.x = a0 * inv; r.y = a1 * inv; r.z = a2 * inv; r.w = 0.f;
        int j = jt * 4 + jl;
        g_F[((b * G0 + k) * G0 + j) * G0 + i] = r;
    }
}

// ---------------- Kernel B: separable flow + fast-path grid_sample -----------
// Block = (32 x, 8 h) tile at fixed (d, b).
// Stage A (48 thr): k-blend  G[j][i] over 4 j x 12 i.
// Stage B (96 thr): j-blend  R[ty][i] per output row (8 rows x 12 i).
// Per voxel: 2 LDS.128 + i-lerp, then one-base immediate-offset 8-tap gather.
__global__ __launch_bounds__(256) void warp_kernel(const float* __restrict__ mask,
                                                   float* __restrict__ out) {
    __shared__ float4 sG[4 * 12];   // k-blended  [j][i]
    __shared__ float4 sR[8 * 12];   // j,k-blended per row [ty][i]

    int tid = threadIdx.x;
    int tx  = tid & 31;
    int ty  = tid >> 5;
    int xt  = blockIdx.x & 3;
    int ht  = blockIdx.x >> 2;
    int d   = blockIdx.y;
    int b   = blockIdx.z;
    int x0  = xt << 5;
    int h0  = ht << 3;

    const float scale = (float)G0 / (float)DHW;  // 0.3125

    // block-uniform k window
    float ck = fmaxf(((float)d + 0.5f) * scale - 0.5f, 0.0f);
    int k0 = min((int)ck, G0 - 1); int k1 = min(k0 + 1, G0 - 1);
    float fk = ck - (float)k0;

    float cj0 = fmaxf(((float)h0 + 0.5f) * scale - 0.5f, 0.0f);
    int j_base = min((int)cj0, G0 - 1);
    float ci0 = fmaxf(((float)x0 + 0.5f) * scale - 0.5f, 0.0f);
    int i_base = min((int)ci0, G0 - 1);

    // ---- stage A: k-blend 48 entries ----
    if (tid < 48) {
        int li = tid % 12;
        int lj = tid / 12;
        int ri = min(i_base + li, G0 - 1);
        int rj = min(j_base + lj, G0 - 1);
        float4 a = g_F[((b * G0 + k0) * G0 + rj) * G0 + ri];
        float4 c = g_F[((b * G0 + k1) * G0 + rj) * G0 + ri];
        float4 g;
        g.x = fmaf(fk, c.x - a.x, a.x);
        g.y = fmaf(fk, c.y - a.y, a.y);
        g.z = fmaf(fk, c.z - a.z, a.z);
        g.w = 0.f;
        sG[tid] = g;
    }
    __syncthreads();

    // ---- stage B: j-blend into 8 rows ----
    if (tid < 96) {
        int li = tid % 12;
        int ry = tid / 12;
        int h  = h0 + ry;
        float cj = fmaxf(((float)h + 0.5f) * scale - 0.5f, 0.0f);
        int j0 = min((int)cj, G0 - 1);
        float fj = cj - (float)j0;
        int t0 = j0 - j_base;
        int t1 = min(j0 + 1, G0 - 1) - j_base;
        float4 a = sG[t0 * 12 + li];
        float4 c = sG[t1 * 12 + li];
        float4 r;
        r.x = fmaf(fj, c.x - a.x, a.x);
        r.y = fmaf(fj, c.y - a.y, a.y);
        r.z = fmaf(fj, c.z - a.z, a.z);
        r.w = 0.f;
        sR[ry * 12 + li] = r;
    }
    __syncthreads();

    // ---- per-voxel: i-lerp of the row ----
    int x = x0 + tx;
    int h = h0 + ty;
    float ci = fmaxf(((float)x + 0.5f) * scale - 0.5f, 0.0f);
    int i0 = min((int)ci, G0 - 1);
    float fi = ci - (float)i0;
    int s0 = i0 - i_base;
    int s1 = min(i0 + 1, G0 - 1) - i_base;

    float4 A = sR[ty * 12 + s0];
    float4 Bv = sR[ty * 12 + s1];
    float f0 = fmaf(fi, Bv.x - A.x, A.x);
    float f1 = fmaf(fi, Bv.y - A.y, A.y);
    float f2 = fmaf(fi, Bv.z - A.z, A.z);

    // warped grid coords -> sample space
    const float lstep = 2.0f / (float)(DHW - 1);
    float gx = fmaf((float)x, lstep, -1.0f) + f0;
    float gy = fmaf((float)h, lstep, -1.0f) + f1;
    float gz = fmaf((float)d, lstep, -1.0f) + f2;

    float xs = fmaf(gx, 64.0f, 63.5f);
    float ys = fmaf(gy, 64.0f, 63.5f);
    float zs = fmaf(gz, 64.0f, 63.5f);

    int ix = (int)floorf(xs); float fx = xs - (float)ix;
    int iy = (int)floorf(ys); float fy = ys - (float)iy;
    int iz = (int)floorf(zs); float fz = zs - (float)iz;

    const float* mb = mask + b * (DHW * DHW * DHW);

    float acc;
    if (((unsigned)ix < 127u) & ((unsigned)iy < 127u) & ((unsigned)iz < 127u)) {
        // fast path: all 8 taps in-bounds; 7 lerps, immediate-offset loads
        const float* p = mb + ((iz << 14) + (iy << 7) + ix);
        float m000 = p[0],      m001 = p[1];
        float m010 = p[128],    m011 = p[129];
        float m100 = p[16384],  m101 = p[16385];
        float m110 = p[16512],  m111 = p[16513];
        float a00 = fmaf(fx, m001 - m000, m000);
        float a01 = fmaf(fx, m011 - m010, m010);
        float a10 = fmaf(fx, m101 - m100, m100);
        float a11 = fmaf(fx, m111 - m110, m110);
        float b0  = fmaf(fy, a01 - a00, a00);
        float b1  = fmaf(fy, a11 - a10, a10);
        acc = fmaf(fz, b1 - b0, b0);
    } else {
        // boundary path: zero padding
        float qx = 1.0f - fx, qy = 1.0f - fy, qz = 1.0f - fz;
        acc = 0.0f;
#pragma unroll
        for (int dz = 0; dz < 2; dz++) {
            int zi = iz + dz;
            if ((unsigned)zi >= (unsigned)DHW) continue;
            float wz = dz ? fz : qz;
            const float* mz = mb + (zi << 14);
#pragma unroll
            for (int dy = 0; dy < 2; dy++) {
                int yi = iy + dy;
                if ((unsigned)yi >= (unsigned)DHW) continue;
                float wzy = wz * (dy ? fy : qy);
                const float* mzy = mz + (yi << 7);
#pragma unroll
                for (int dx = 0; dx < 2; dx++) {
                    int xi = ix + dx;
                    if ((unsigned)xi >= (unsigned)DHW) continue;
                    acc = fmaf(wzy * (dx ? fx : qx), mzy[xi], acc);
                }
            }
        }
    }

    out[(((b << 7) | d) << 14) | (h << 7) | x] = acc;
}

// ---------------- launch ------------------------------------------------------
extern "C" void kernel_launch(void* const* d_in, const int* in_sizes, int n_in,
                              void* d_out, int out_size) {
    const float* mask = (const float*)d_in[0];
    const float* cpc  = (const float*)d_in[1];
    const float* cpo  = (const float*)d_in[2];
    float* out = (float*)d_out;

    table_kernel<<<(B * N * G0 + 255) / 256, 256>>>(cpc, cpo);
    coarse_kernel<<<dim3(G0 / 4, G0, B), 256>>>();
    warp_kernel<<<dim3(64, DHW, B), 256>>>(mask, out);
}